// round 3
// baseline (speedup 1.0000x reference)
#include <cuda_runtime.h>
#include <math.h>

// Problem constants
#define BATCH 128
#define NN    50          // N (permutation size)
#define FDIM  1024
#define HDIM  4096
#define MROWS (BATCH*NN)  // 6400

// Output layout (floats)
#define PSI_OFF  0
#define PERM_OFF (BATCH*NN*NN)        // 320000
#define X_OFF    (2*BATCH*NN*NN)      // 640000
#define DIST_OFF (3*BATCH*NN*NN)      // 960000

// Scratch (device globals: allocation-free rule)
__device__ float g_h[(size_t)MROWS * HDIM];   // hidden activations, ~105 MB
__device__ float g_P[BATCH * NN * NN];        // psi workspace

// ---------------------------------------------------------------------------
// Kernel 1: C = leaky_relu(x @ W1 + b1)
// M=6400, N=4096, K=1024. Classic 128x128x16 SGEMM, 8x8 per thread, 256 thr.
// ---------------------------------------------------------------------------
#define BM 128
#define BN 128
#define BK 16
#define TM 8
#define TN 8

__global__ __launch_bounds__(256) void gemm1_kernel(
    const float* __restrict__ A,     // [6400,1024]
    const float* __restrict__ W,     // [1024,4096]
    const float* __restrict__ bias,  // [4096]
    float* __restrict__ C)           // [6400,4096]
{
    __shared__ float As[BK][BM];
    __shared__ float Bs[BK][BN];

    const int bx = blockIdx.x;   // N tile: 0..31
    const int by = blockIdx.y;   // M tile: 0..49
    const int tid = threadIdx.x;
    const int tx = tid & 15;
    const int ty = tid >> 4;

    const float* Ab = A + (size_t)by * BM * FDIM;
    const float* Wb = W + (size_t)bx * BN;

    float acc[TM][TN];
#pragma unroll
    for (int i = 0; i < TM; i++)
#pragma unroll
        for (int j = 0; j < TN; j++) acc[i][j] = 0.f;

    const int arow = tid >> 2;          // 0..63
    const int acol = (tid & 3) * 4;     // 0,4,8,12
    const int brow = tid >> 5;          // 0..7
    const int bcol = (tid & 31) * 4;    // 0..124

    for (int k0 = 0; k0 < FDIM; k0 += BK) {
        float4 a0 = *(const float4*)(Ab + (size_t)arow * FDIM + k0 + acol);
        float4 a1 = *(const float4*)(Ab + (size_t)(arow + 64) * FDIM + k0 + acol);
        As[acol + 0][arow] = a0.x;  As[acol + 1][arow] = a0.y;
        As[acol + 2][arow] = a0.z;  As[acol + 3][arow] = a0.w;
        As[acol + 0][arow + 64] = a1.x;  As[acol + 1][arow + 64] = a1.y;
        As[acol + 2][arow + 64] = a1.z;  As[acol + 3][arow + 64] = a1.w;

        float4 b0 = *(const float4*)(Wb + (size_t)(k0 + brow) * HDIM + bcol);
        float4 b1 = *(const float4*)(Wb + (size_t)(k0 + brow + 8) * HDIM + bcol);
        *(float4*)&Bs[brow][bcol]     = b0;
        *(float4*)&Bs[brow + 8][bcol] = b1;

        __syncthreads();

#pragma unroll
        for (int k = 0; k < BK; k++) {
            float ar[TM], br[TN];
            float4 av0 = *(const float4*)&As[k][ty * TM];
            float4 av1 = *(const float4*)&As[k][ty * TM + 4];
            ar[0]=av0.x; ar[1]=av0.y; ar[2]=av0.z; ar[3]=av0.w;
            ar[4]=av1.x; ar[5]=av1.y; ar[6]=av1.z; ar[7]=av1.w;
            float4 bv0 = *(const float4*)&Bs[k][tx * TN];
            float4 bv1 = *(const float4*)&Bs[k][tx * TN + 4];
            br[0]=bv0.x; br[1]=bv0.y; br[2]=bv0.z; br[3]=bv0.w;
            br[4]=bv1.x; br[5]=bv1.y; br[6]=bv1.z; br[7]=bv1.w;
#pragma unroll
            for (int i = 0; i < TM; i++)
#pragma unroll
                for (int j = 0; j < TN; j++)
                    acc[i][j] = fmaf(ar[i], br[j], acc[i][j]);
        }
        __syncthreads();
    }

#pragma unroll
    for (int i = 0; i < TM; i++) {
        int gm = by * BM + ty * TM + i;
#pragma unroll
        for (int j = 0; j < TN; j++) {
            int gn = bx * BN + tx * TN + j;
            float c = acc[i][j] + bias[gn];
            c = (c > 0.f) ? c : 0.01f * c;   // leaky_relu, slope 0.01
            C[(size_t)gm * HDIM + gn] = c;
        }
    }
}

// ---------------------------------------------------------------------------
// Kernel 2: P = exp(leaky_relu(h @ W2 + b2))   [6400 rows, 50 cols]
// ---------------------------------------------------------------------------
__global__ __launch_bounds__(256) void gemm2_kernel(
    const float* __restrict__ h,    // [6400,4096]
    const float* __restrict__ W2,   // [4096,50]
    const float* __restrict__ b2,   // [50]
    float* __restrict__ P)          // [128,50,50] flattened rows
{
    __shared__ float sh[HDIM];
    __shared__ float red[4][64];

    const int r = blockIdx.x;
    const int tid = threadIdx.x;
    const float* hr = h + (size_t)r * HDIM;

    for (int k = tid; k < HDIM; k += 256) sh[k] = hr[k];
    __syncthreads();

    const int nx = tid & 63;
    const int ky = tid >> 6;

    float a0 = 0.f, a1 = 0.f, a2 = 0.f, a3 = 0.f;
    if (nx < NN) {
        const float* wcol = W2 + nx;
        const int kbase = ky * 1024;
#pragma unroll 4
        for (int k = kbase; k < kbase + 1024; k += 4) {
            a0 = fmaf(sh[k + 0], wcol[(k + 0) * NN], a0);
            a1 = fmaf(sh[k + 1], wcol[(k + 1) * NN], a1);
            a2 = fmaf(sh[k + 2], wcol[(k + 2) * NN], a2);
            a3 = fmaf(sh[k + 3], wcol[(k + 3) * NN], a3);
        }
    }
    red[ky][nx] = (a0 + a1) + (a2 + a3);
    __syncthreads();

    if (tid < NN) {
        float s = red[0][tid] + red[1][tid] + red[2][tid] + red[3][tid] + b2[tid];
        s = (s > 0.f) ? s : 0.01f * s;
        P[(size_t)r * NN + tid] = expf(s);   // TAU = 1
    }
}

// ---------------------------------------------------------------------------
// Kernel 3: Sinkhorn (5 iters), per batch. X == psi since ALPHA=1.0.
// ---------------------------------------------------------------------------
__global__ __launch_bounds__(256) void sinkhorn_kernel(
    float* __restrict__ P, float* __restrict__ out)
{
    __shared__ float sp[NN * NN];
    const int b = blockIdx.x;
    const int tid = threadIdx.x;
    float* Pb = P + (size_t)b * NN * NN;

    for (int i = tid; i < NN * NN; i += 256) sp[i] = Pb[i];
    __syncthreads();

    const int warp = tid >> 5, lane = tid & 31;

    for (int it = 0; it < 5; it++) {
        // normalize rows (sum over axis=2)
        for (int i = warp; i < NN; i += 8) {
            float v0 = sp[i * NN + lane];
            float v1 = (lane + 32 < NN) ? sp[i * NN + lane + 32] : 0.f;
            float s = v0 + v1;
#pragma unroll
            for (int o = 16; o; o >>= 1) s += __shfl_xor_sync(~0u, s, o);
            sp[i * NN + lane] = v0 / s;
            if (lane + 32 < NN) sp[i * NN + lane + 32] = v1 / s;
        }
        __syncthreads();
        // normalize cols (sum over axis=1)
        for (int j = warp; j < NN; j += 8) {
            float v0 = sp[lane * NN + j];
            float v1 = (lane + 32 < NN) ? sp[(lane + 32) * NN + j] : 0.f;
            float s = v0 + v1;
#pragma unroll
            for (int o = 16; o; o >>= 1) s += __shfl_xor_sync(~0u, s, o);
            sp[lane * NN + j] = v0 / s;
            if (lane + 32 < NN) sp[(lane + 32) * NN + j] = v1 / s;
        }
        __syncthreads();
    }

    float* psi_out = out + PSI_OFF + (size_t)b * NN * NN;
    float* x_out   = out + X_OFF   + (size_t)b * NN * NN;
    for (int i = tid; i < NN * NN; i += 256) {
        float v = sp[i];
        Pb[i] = v;
        psi_out[i] = v;
        x_out[i] = v;   // X = (1-1)*perms + 1*psi = psi exactly
    }
}

// ---------------------------------------------------------------------------
// Kernel 4: replicate the reference's BUGGY Hungarian exactly.
// Key insight: the reference never writes `minv` back (mv is a dead copy),
// so it degenerates to a greedy chain walk:
//   - from current j0: mark used; i0 = p[j0]
//   - cur[j] = cost[i0-1,j-1] - u[i0] - v[j] over FREE j
//   - j1 = argmin (lowest-index ties, like np.argmin); delta = cur[j1]
//   - way[j1] = j0  (reference sets way for all free j each iter; only the
//     chain entries are ever read, and those equal "j0 at selection time")
//   - u[p[j]] += delta, v[j] -= delta for ALL used j (incl. j=0)
//   - hop to j1; stop when p[j1]==0; rotate matching along chain.
// float64 arithmetic to match numpy's promotion bit-for-bit.
// One warp per batch. Writes perms + dist.
// ---------------------------------------------------------------------------
__global__ __launch_bounds__(32) void hungarian_kernel(
    const float* __restrict__ P,   // psi [128,50,50]
    float* __restrict__ out)
{
    __shared__ float  sc[NN * NN];           // psi (cost = -psi)
    __shared__ double u[NN + 1], v[NN + 1];
    __shared__ int    p[NN + 1], way[NN + 1];
    __shared__ int    used[NN + 1];
    __shared__ int    s_j0;
    __shared__ int    rtc[NN];

    const int b = blockIdx.x;
    const int lane = threadIdx.x;
    const double INF = 1e18;
    const float* Pb = P + (size_t)b * NN * NN;

    for (int i = lane; i < NN * NN; i += 32) sc[i] = Pb[i];
    for (int j = lane; j <= NN; j += 32) { u[j] = 0.0; v[j] = 0.0; p[j] = 0; }
    __syncwarp();

    for (int i = 1; i <= NN; i++) {
        if (lane == 0) { p[0] = i; s_j0 = 0; }
        for (int j = lane; j <= NN; j += 32) used[j] = 0;
        __syncwarp();

        while (true) {
            const int j0 = s_j0;
            if (lane == 0) used[j0] = 1;
            __syncwarp();

            const int i0 = p[j0];
            const double du = u[i0];

            double best = INF;
            int bestj = NN + 1;

            int jj = lane + 1;                       // 1..32
            if (!used[jj]) {
                double cur = -(double)sc[(i0 - 1) * NN + (jj - 1)] - du - v[jj];
                best = cur; bestj = jj;
            }
            jj = lane + 33;                          // 33..50 (lane < 18)
            if (jj <= NN && !used[jj]) {
                double cur = -(double)sc[(i0 - 1) * NN + (jj - 1)] - du - v[jj];
                if (cur < best) { best = cur; bestj = jj; }  // strict: prefer lower j
            }

            // warp argmin, lowest-index tie-break (matches np.argmin)
#pragma unroll
            for (int o = 16; o; o >>= 1) {
                double ob = __shfl_xor_sync(~0u, best, o);
                int    oj = __shfl_xor_sync(~0u, bestj, o);
                if (ob < best || (ob == best && oj < bestj)) { best = ob; bestj = oj; }
            }
            const double delta = best;
            const int j1 = bestj;
            __syncwarp();   // all reads of u/v done before updates

            // u[p[used]] += delta; v[used] -= delta  (j in 0..NN)
            int ja = lane;
            if (used[ja]) { u[p[ja]] += delta; v[ja] -= delta; }
            ja = lane + 32;
            if (ja <= NN && used[ja]) { u[p[ja]] += delta; v[ja] -= delta; }
            __syncwarp();

            if (lane == 0) { way[j1] = j0; s_j0 = j1; }
            __syncwarp();
            if (p[j1] == 0) break;
        }

        // rotate matching along the visit chain (serial, tiny)
        if (lane == 0) {
            int j0 = s_j0;
            while (j0) { int jn = way[j0]; p[j0] = p[jn]; j0 = jn; }
        }
        __syncwarp();
    }

    // row_to_col
    {
        int j = lane + 1;
        if (p[j] > 0) rtc[p[j] - 1] = j - 1;
        j = lane + 33;
        if (j <= NN && p[j] > 0) rtc[p[j] - 1] = j - 1;
    }
    __syncwarp();

    // perms (zero then one-hot) and dist
    float* pb = out + PERM_OFF + (size_t)b * NN * NN;
    for (int i = lane; i < NN * NN; i += 32) pb[i] = 0.f;
    __syncwarp();
    if (lane == 0) {
        float dsum = 0.f;
        for (int r = 0; r < NN; r++) {
            int cidx = rtc[r];
            pb[r * NN + cidx] = 1.0f;
            dsum += sc[r * NN + cidx];
        }
        out[DIST_OFF + b] = dsum / (float)NN;
    }
}

// ---------------------------------------------------------------------------
extern "C" void kernel_launch(void* const* d_in, const int* in_sizes, int n_in,
                              void* d_out, int out_size)
{
    (void)in_sizes; (void)n_in; (void)out_size;
    const float* x  = (const float*)d_in[0];
    const float* W1 = (const float*)d_in[1];
    const float* b1 = (const float*)d_in[2];
    const float* W2 = (const float*)d_in[3];
    const float* b2 = (const float*)d_in[4];
    float* out = (float*)d_out;

    float* h;  cudaGetSymbolAddress((void**)&h,  g_h);
    float* P;  cudaGetSymbolAddress((void**)&P,  g_P);

    dim3 g1(HDIM / BN, MROWS / BM);          // 32 x 50
    gemm1_kernel<<<g1, 256>>>(x, W1, b1, h);
    gemm2_kernel<<<MROWS, 256>>>(h, W2, b2, P);
    sinkhorn_kernel<<<BATCH, 256>>>(P, out);
    hungarian_kernel<<<BATCH, 32>>>(P, out);
}

// round 5
// speedup vs baseline: 1.2406x; 1.2406x over previous
#include <cuda_runtime.h>
#include <cuda_bf16.h>
#include <math.h>
#include <stdint.h>

#define BATCH 128
#define NN    50
#define FDIM  1024
#define HDIM  4096
#define MROWS (BATCH*NN)
#define KCAT  (3*FDIM)          // 3072: slots [a0,a0,a1] x [b0,b1,b0]

#define PSI_OFF  0
#define PERM_OFF (BATCH*NN*NN)
#define X_OFF    (2*BATCH*NN*NN)
#define DIST_OFF (3*BATCH*NN*NN)

__device__ float         g_h[(size_t)MROWS * HDIM];
__device__ float         g_P[BATCH * NN * NN];
__device__ __nv_bfloat16 g_Acat[(size_t)MROWS * KCAT];
__device__ __nv_bfloat16 g_Bcat[(size_t)HDIM * KCAT];

__device__ __forceinline__ uint32_t smem_u32(const void* p) {
    uint32_t a;
    asm("{ .reg .u64 t; cvta.to.shared.u64 t, %1; cvt.u32.u64 %0, t; }" : "=r"(a) : "l"(p));
    return a;
}
#define SW128(o) ((o) ^ (((o) >> 3) & 0x70))
#define CPA16(dst, src) asm volatile("cp.async.cg.shared.global [%0], [%1], 16;" :: "r"(dst), "l"(src) : "memory")
#define CPA_COMMIT()    asm volatile("cp.async.commit_group;" ::: "memory")
#define CPA_WAIT2()     asm volatile("cp.async.wait_group 2;" ::: "memory")

__device__ __forceinline__ void ldm_x4(uint32_t* r, uint32_t addr) {
    asm volatile("ldmatrix.sync.aligned.m8n8.x4.shared.b16 {%0,%1,%2,%3}, [%4];"
        : "=r"(r[0]), "=r"(r[1]), "=r"(r[2]), "=r"(r[3]) : "r"(addr));
}
__device__ __forceinline__ void mma_bf16(float* d, const uint32_t* a, const uint32_t* b) {
    asm volatile("mma.sync.aligned.m16n8k16.row.col.f32.bf16.bf16.f32 "
        "{%0,%1,%2,%3}, {%4,%5,%6,%7}, {%8,%9}, {%0,%1,%2,%3};"
        : "+f"(d[0]), "+f"(d[1]), "+f"(d[2]), "+f"(d[3])
        : "r"(a[0]), "r"(a[1]), "r"(a[2]), "r"(a[3]), "r"(b[0]), "r"(b[1]));
}

// ---------------- split kernels (2-term bf16 split) ----------------
__global__ __launch_bounds__(256) void split_x_kernel(const float* __restrict__ x, __nv_bfloat16* __restrict__ A) {
    int idx = blockIdx.x * 256 + threadIdx.x;       // < 6400*1024
    float a = x[idx];
    __nv_bfloat16 h0 = __float2bfloat16(a);
    __nv_bfloat16 h1 = __float2bfloat16(a - __bfloat162float(h0));
    __nv_bfloat16* row = A + (size_t)(idx >> 10) * KCAT + (idx & 1023);
    row[0] = h0; row[1024] = h0; row[2048] = h1;
}
__global__ __launch_bounds__(256) void split_w_kernel(const float* __restrict__ W1, __nv_bfloat16* __restrict__ B) {
    __shared__ __nv_bfloat16 t0[32][33], t1[32][33];
    const int tx = threadIdx.x, ty = threadIdx.y;   // (32,8)
    const int n0 = blockIdx.x * 32, k0 = blockIdx.y * 32;
#pragma unroll
    for (int i = 0; i < 4; i++) {
        int k = ty + i * 8;
        float w = W1[(size_t)(k0 + k) * HDIM + n0 + tx];
        __nv_bfloat16 h0 = __float2bfloat16(w);
        t0[k][tx] = h0;
        t1[k][tx] = __float2bfloat16(w - __bfloat162float(h0));
    }
    __syncthreads();
#pragma unroll
    for (int i = 0; i < 4; i++) {
        int n = ty + i * 8;
        __nv_bfloat16 b0 = t0[tx][n], b1 = t1[tx][n];
        __nv_bfloat16* row = B + (size_t)(n0 + n) * KCAT + k0 + tx;
        row[0] = b0; row[1024] = b1; row[2048] = b0;
    }
}

// ---------------- GEMM1: mma.sync bf16, CTA 128x128, BK=64, 4 stages -------
#define G1_STAGES 4
#define G1_BKE    64
#define G1_KIT    (KCAT / G1_BKE)     // 48
#define G1_STB    32768               // A 16KB + B 16KB per stage
#define G1_SMEM   (G1_STAGES * G1_STB)

__global__ __launch_bounds__(256, 1) void gemm1_mma_kernel(
    const __nv_bfloat16* __restrict__ A, const __nv_bfloat16* __restrict__ B,
    const float* __restrict__ bias, float* __restrict__ C)
{
    extern __shared__ char sm[];
    const uint32_t sb = smem_u32(sm);
    const int tid = threadIdx.x, lane = tid & 31, wid = tid >> 5;
    const int m0 = blockIdx.x * 128, n0 = blockIdx.y * 128;
    const int wm = wid >> 2, wn = wid & 3;          // 2 x 4 warps

    // producer mapping: thread -> (row, half); 4 x 16B for A, 4 x 16B for B
    const int lrow = tid >> 1, lhalf = tid & 1;
    const __nv_bfloat16* Ag = A + (size_t)(m0 + lrow) * KCAT + lhalf * 32;
    const __nv_bfloat16* Bg = B + (size_t)(n0 + lrow) * KCAT + lhalf * 32;
    uint32_t swo[4];
#pragma unroll
    for (int j = 0; j < 4; j++) {
        uint32_t o = lrow * 128 + lhalf * 64 + j * 16;
        swo[j] = SW128(o);
    }

#define G1_ISSUE(it) do { \
    const int st_ = (it) % G1_STAGES; const int ke_ = (it) * G1_BKE; \
    const uint32_t so_ = sb + st_ * G1_STB; \
    _Pragma("unroll") \
    for (int j = 0; j < 4; j++) { \
        CPA16(so_ + swo[j],         Ag + ke_ + j * 8); \
        CPA16(so_ + 16384 + swo[j], Bg + ke_ + j * 8); \
    } } while (0)

    G1_ISSUE(0); CPA_COMMIT();
    G1_ISSUE(1); CPA_COMMIT();
    G1_ISSUE(2); CPA_COMMIT();

    float acc[4][4][4];
#pragma unroll
    for (int i = 0; i < 4; i++)
#pragma unroll
        for (int j = 0; j < 4; j++)
#pragma unroll
            for (int q = 0; q < 4; q++) acc[i][j][q] = 0.f;

    // per-lane ldmatrix address components
    const int a_row = wm * 64 + (lane & 7) + 8 * ((lane >> 3) & 1);
    const uint32_t a_kb = (lane >> 4) * 16;
    const int b_row = wn * 32 + (lane & 7) + 8 * (lane >> 4);
    const uint32_t b_kb = ((lane >> 3) & 1) * 16;

    for (int it = 0; it < G1_KIT; it++) {
        CPA_WAIT2();
        __syncthreads();
        if (it + 3 < G1_KIT) G1_ISSUE(it + 3);
        CPA_COMMIT();

        const uint32_t ao = sb + (it % G1_STAGES) * G1_STB;
        const uint32_t bo = ao + 16384;
#pragma unroll
        for (int kk = 0; kk < 4; kk++) {
            uint32_t af[4][4], bf[2][4];
#pragma unroll
            for (int mt = 0; mt < 4; mt++) {
                uint32_t o = (uint32_t)(a_row + mt * 16) * 128 + kk * 32 + a_kb;
                ldm_x4(af[mt], ao + SW128(o));
            }
#pragma unroll
            for (int np = 0; np < 2; np++) {
                uint32_t o = (uint32_t)(b_row + np * 16) * 128 + kk * 32 + b_kb;
                ldm_x4(bf[np], bo + SW128(o));
            }
#pragma unroll
            for (int mt = 0; mt < 4; mt++)
#pragma unroll
                for (int nt = 0; nt < 4; nt++)
                    mma_bf16(acc[mt][nt], af[mt], &bf[nt >> 1][(nt & 1) * 2]);
        }
    }
    __syncthreads();

    // epilogue: bias + leaky_relu, fp32 store
    const int erow = lane >> 2, ecol = (lane & 3) * 2;
#pragma unroll
    for (int mt = 0; mt < 4; mt++) {
        const int r0 = m0 + wm * 64 + mt * 16 + erow;
#pragma unroll
        for (int nt = 0; nt < 4; nt++) {
            const int c = n0 + wn * 32 + nt * 8 + ecol;
            float2 bb = *(const float2*)(bias + c);
            float v0 = acc[mt][nt][0] + bb.x, v1 = acc[mt][nt][1] + bb.y;
            float v2 = acc[mt][nt][2] + bb.x, v3 = acc[mt][nt][3] + bb.y;
            float2 o0 = { v0 > 0.f ? v0 : 0.01f * v0, v1 > 0.f ? v1 : 0.01f * v1 };
            float2 o1 = { v2 > 0.f ? v2 : 0.01f * v2, v3 > 0.f ? v3 : 0.01f * v3 };
            *(float2*)(C + (size_t)r0 * HDIM + c) = o0;
            *(float2*)(C + (size_t)(r0 + 8) * HDIM + c) = o1;
        }
    }
#undef G1_ISSUE
}

// ---------------- GEMM2: one block per batch, K chunks of 64 ----------------
__global__ __launch_bounds__(256) void gemm2_kernel(
    const float* __restrict__ h, const float* __restrict__ W2,
    const float* __restrict__ b2, float* __restrict__ P)
{
    __shared__ float hs[NN][65];
    __shared__ float ws[64][51];
    const int b = blockIdx.x, tid = threadIdx.x;
    const int rg = tid / 10, cg = tid % 10;       // tid<250 active
    const float* hb = h + (size_t)b * NN * HDIM;

    float acc[2][5];
#pragma unroll
    for (int i = 0; i < 2; i++)
#pragma unroll
        for (int j = 0; j < 5; j++) acc[i][j] = 0.f;

    for (int k0 = 0; k0 < HDIM; k0 += 64) {
        __syncthreads();
        for (int idx = tid; idx < NN * 64; idx += 256) {
            int r = idx >> 6, k = idx & 63;
            hs[r][k] = hb[(size_t)r * HDIM + k0 + k];
        }
        const float* wsrc = W2 + (size_t)k0 * NN;
        for (int idx = tid; idx < 64 * NN; idx += 256)
            ws[idx / NN][idx % NN] = wsrc[idx];
        __syncthreads();
        if (tid < 250) {
            const int r0 = rg * 2, c0 = cg * 5;
#pragma unroll 4
            for (int k = 0; k < 64; k++) {
                float a0 = hs[r0][k], a1 = hs[r0 + 1][k];
#pragma unroll
                for (int j = 0; j < 5; j++) {
                    float w = ws[k][c0 + j];
                    acc[0][j] = fmaf(a0, w, acc[0][j]);
                    acc[1][j] = fmaf(a1, w, acc[1][j]);
                }
            }
        }
    }
    if (tid < 250) {
        const int r0 = rg * 2, c0 = cg * 5;
#pragma unroll
        for (int i = 0; i < 2; i++)
#pragma unroll
            for (int j = 0; j < 5; j++) {
                float s = acc[i][j] + b2[c0 + j];
                s = (s > 0.f) ? s : 0.01f * s;
                P[(size_t)b * NN * NN + (r0 + i) * NN + c0 + j] = expf(s);
            }
    }
}

// ---------------- Sinkhorn (unchanged, known-good) ----------------
__global__ __launch_bounds__(256) void sinkhorn_kernel(float* __restrict__ P, float* __restrict__ out) {
    __shared__ float sp[NN * NN];
    const int b = blockIdx.x, tid = threadIdx.x;
    float* Pb = P + (size_t)b * NN * NN;
    for (int i = tid; i < NN * NN; i += 256) sp[i] = Pb[i];
    __syncthreads();
    const int warp = tid >> 5, lane = tid & 31;
    for (int it = 0; it < 5; it++) {
        for (int i = warp; i < NN; i += 8) {
            float v0 = sp[i * NN + lane];
            float v1 = (lane + 32 < NN) ? sp[i * NN + lane + 32] : 0.f;
            float s = v0 + v1;
#pragma unroll
            for (int o = 16; o; o >>= 1) s += __shfl_xor_sync(~0u, s, o);
            sp[i * NN + lane] = v0 / s;
            if (lane + 32 < NN) sp[i * NN + lane + 32] = v1 / s;
        }
        __syncthreads();
        for (int j = warp; j < NN; j += 8) {
            float v0 = sp[lane * NN + j];
            float v1 = (lane + 32 < NN) ? sp[(lane + 32) * NN + j] : 0.f;
            float s = v0 + v1;
#pragma unroll
            for (int o = 16; o; o >>= 1) s += __shfl_xor_sync(~0u, s, o);
            sp[lane * NN + j] = v0 / s;
            if (lane + 32 < NN) sp[(lane + 32) * NN + j] = v1 / s;
        }
        __syncthreads();
    }
    float* psi_out = out + PSI_OFF + (size_t)b * NN * NN;
    float* x_out   = out + X_OFF   + (size_t)b * NN * NN;
    for (int i = tid; i < NN * NN; i += 256) {
        float v = sp[i];
        Pb[i] = v; psi_out[i] = v; x_out[i] = v;
    }
}

// ---------------- Hungarian (reference's buggy greedy; unchanged) ----------
__global__ __launch_bounds__(32) void hungarian_kernel(const float* __restrict__ P, float* __restrict__ out) {
    __shared__ float  sc[NN * NN];
    __shared__ double u[NN + 1], v[NN + 1];
    __shared__ int    p[NN + 1], way[NN + 1], used[NN + 1], s_j0, rtc[NN];
    const int b = blockIdx.x, lane = threadIdx.x;
    const double INF = 1e18;
    const float* Pb = P + (size_t)b * NN * NN;
    for (int i = lane; i < NN * NN; i += 32) sc[i] = Pb[i];
    for (int j = lane; j <= NN; j += 32) { u[j] = 0.0; v[j] = 0.0; p[j] = 0; }
    __syncwarp();
    for (int i = 1; i <= NN; i++) {
        if (lane == 0) { p[0] = i; s_j0 = 0; }
        for (int j = lane; j <= NN; j += 32) used[j] = 0;
        __syncwarp();
        while (true) {
            const int j0 = s_j0;
            if (lane == 0) used[j0] = 1;
            __syncwarp();
            const int i0 = p[j0];
            const double du = u[i0];
            double best = INF; int bestj = NN + 1;
            int jj = lane + 1;
            if (!used[jj]) { best = -(double)sc[(i0 - 1) * NN + (jj - 1)] - du - v[jj]; bestj = jj; }
            jj = lane + 33;
            if (jj <= NN && !used[jj]) {
                double cur = -(double)sc[(i0 - 1) * NN + (jj - 1)] - du - v[jj];
                if (cur < best) { best = cur; bestj = jj; }
            }
#pragma unroll
            for (int o = 16; o; o >>= 1) {
                double ob = __shfl_xor_sync(~0u, best, o);
                int    oj = __shfl_xor_sync(~0u, bestj, o);
                if (ob < best || (ob == best && oj < bestj)) { best = ob; bestj = oj; }
            }
            const double delta = best; const int j1 = bestj;
            __syncwarp();
            int ja = lane;
            if (used[ja]) { u[p[ja]] += delta; v[ja] -= delta; }
            ja = lane + 32;
            if (ja <= NN && used[ja]) { u[p[ja]] += delta; v[ja] -= delta; }
            __syncwarp();
            if (lane == 0) { way[j1] = j0; s_j0 = j1; }
            __syncwarp();
            if (p[j1] == 0) break;
        }
        if (lane == 0) {
            int j0 = s_j0;
            while (j0) { int jn = way[j0]; p[j0] = p[jn]; j0 = jn; }
        }
        __syncwarp();
    }
    {
        int j = lane + 1;
        if (p[j] > 0) rtc[p[j] - 1] = j - 1;
        j = lane + 33;
        if (j <= NN && p[j] > 0) rtc[p[j] - 1] = j - 1;
    }
    __syncwarp();
    float* pb = out + PERM_OFF + (size_t)b * NN * NN;
    for (int i = lane; i < NN * NN; i += 32) pb[i] = 0.f;
    __syncwarp();
    if (lane == 0) {
        float dsum = 0.f;
        for (int r = 0; r < NN; r++) { int c = rtc[r]; pb[r * NN + c] = 1.0f; dsum += sc[r * NN + c]; }
        out[DIST_OFF + b] = dsum / (float)NN;
    }
}

// ---------------------------------------------------------------------------
extern "C" void kernel_launch(void* const* d_in, const int* in_sizes, int n_in,
                              void* d_out, int out_size)
{
    (void)in_sizes; (void)n_in; (void)out_size;
    const float* x  = (const float*)d_in[0];
    const float* W1 = (const float*)d_in[1];
    const float* b1 = (const float*)d_in[2];
    const float* W2 = (const float*)d_in[3];
    const float* b2 = (const float*)d_in[4];
    float* out = (float*)d_out;

    float* h;  cudaGetSymbolAddress((void**)&h,  g_h);
    float* P;  cudaGetSymbolAddress((void**)&P,  g_P);
    __nv_bfloat16* Ac; cudaGetSymbolAddress((void**)&Ac, g_Acat);
    __nv_bfloat16* Bc; cudaGetSymbolAddress((void**)&Bc, g_Bcat);

    cudaFuncSetAttribute(gemm1_mma_kernel, cudaFuncAttributeMaxDynamicSharedMemorySize, G1_SMEM);

    split_x_kernel<<<MROWS * FDIM / 256, 256>>>(x, Ac);
    split_w_kernel<<<dim3(HDIM / 32, FDIM / 32), dim3(32, 8)>>>(W1, Bc);
    gemm1_mma_kernel<<<dim3(MROWS / 128, HDIM / 128), 256, G1_SMEM>>>(Ac, Bc, b1, h);
    gemm2_kernel<<<BATCH, 256>>>(h, W2, b2, P);
    sinkhorn_kernel<<<BATCH, 256>>>(P, out);
    hungarian_kernel<<<BATCH, 32>>>(P, out);
}

// round 7
// speedup vs baseline: 1.3779x; 1.1106x over previous
#include <cuda_runtime.h>
#include <cuda_bf16.h>
#include <math.h>
#include <stdint.h>

#define BATCH 128
#define NN    50
#define FDIM  1024
#define HDIM  4096
#define MROWS (BATCH*NN)
#define KCAT  (3*FDIM)          // 3072: slots [a0,a0,a1] x [b0,b1,b0]

#define PSI_OFF  0
#define PERM_OFF (BATCH*NN*NN)
#define X_OFF    (2*BATCH*NN*NN)
#define DIST_OFF (3*BATCH*NN*NN)

__device__ float         g_h[(size_t)MROWS * HDIM];
__device__ float         g_P[BATCH * NN * NN];
__device__ __nv_bfloat16 g_Acat[(size_t)MROWS * KCAT];
__device__ __nv_bfloat16 g_Bcat[(size_t)HDIM * KCAT];

__device__ __forceinline__ uint32_t smem_u32(const void* p) {
    uint32_t a;
    asm("{ .reg .u64 t; cvta.to.shared.u64 t, %1; cvt.u32.u64 %0, t; }" : "=r"(a) : "l"(p));
    return a;
}
#define SW128(o) ((o) ^ (((o) >> 3) & 0x70))
#define CPA16(dst, src) asm volatile("cp.async.cg.shared.global [%0], [%1], 16;" :: "r"(dst), "l"(src) : "memory")
#define CPA_COMMIT()    asm volatile("cp.async.commit_group;" ::: "memory")
#define CPA_WAIT2()     asm volatile("cp.async.wait_group 2;" ::: "memory")

__device__ __forceinline__ void ldm_x4(uint32_t* r, uint32_t addr) {
    asm volatile("ldmatrix.sync.aligned.m8n8.x4.shared.b16 {%0,%1,%2,%3}, [%4];"
        : "=r"(r[0]), "=r"(r[1]), "=r"(r[2]), "=r"(r[3]) : "r"(addr));
}
__device__ __forceinline__ void mma_bf16(float* d, const uint32_t* a, const uint32_t* b) {
    asm volatile("mma.sync.aligned.m16n8k16.row.col.f32.bf16.bf16.f32 "
        "{%0,%1,%2,%3}, {%4,%5,%6,%7}, {%8,%9}, {%0,%1,%2,%3};"
        : "+f"(d[0]), "+f"(d[1]), "+f"(d[2]), "+f"(d[3])
        : "r"(a[0]), "r"(a[1]), "r"(a[2]), "r"(a[3]), "r"(b[0]), "r"(b[1]));
}

// ---------------- split kernels (2-term bf16 split) ----------------
__global__ __launch_bounds__(256) void split_x_kernel(const float* __restrict__ x, __nv_bfloat16* __restrict__ A) {
    int idx = blockIdx.x * 256 + threadIdx.x;
    float a = x[idx];
    __nv_bfloat16 h0 = __float2bfloat16(a);
    __nv_bfloat16 h1 = __float2bfloat16(a - __bfloat162float(h0));
    __nv_bfloat16* row = A + (size_t)(idx >> 10) * KCAT + (idx & 1023);
    row[0] = h0; row[1024] = h0; row[2048] = h1;
}
__global__ __launch_bounds__(256) void split_w_kernel(const float* __restrict__ W1, __nv_bfloat16* __restrict__ B) {
    __shared__ __nv_bfloat16 t0[32][33], t1[32][33];
    const int tx = threadIdx.x, ty = threadIdx.y;   // (32,8)
    const int n0 = blockIdx.x * 32, k0 = blockIdx.y * 32;
#pragma unroll
    for (int i = 0; i < 4; i++) {
        int k = ty + i * 8;
        float w = W1[(size_t)(k0 + k) * HDIM + n0 + tx];
        __nv_bfloat16 h0 = __float2bfloat16(w);
        t0[k][tx] = h0;
        t1[k][tx] = __float2bfloat16(w - __bfloat162float(h0));
    }
    __syncthreads();
#pragma unroll
    for (int i = 0; i < 4; i++) {
        int n = ty + i * 8;
        __nv_bfloat16 b0 = t0[tx][n], b1 = t1[tx][n];
        __nv_bfloat16* row = B + (size_t)(n0 + n) * KCAT + k0 + tx;
        row[0] = b0; row[1024] = b1; row[2048] = b0;
    }
}

// ---------------- GEMM1: mma.sync bf16 (unchanged, passing) ----------------
#define G1_STAGES 4
#define G1_BKE    64
#define G1_KIT    (KCAT / G1_BKE)
#define G1_STB    32768
#define G1_SMEM   (G1_STAGES * G1_STB)

__global__ __launch_bounds__(256, 1) void gemm1_mma_kernel(
    const __nv_bfloat16* __restrict__ A, const __nv_bfloat16* __restrict__ B,
    const float* __restrict__ bias, float* __restrict__ C)
{
    extern __shared__ char sm[];
    const uint32_t sb = smem_u32(sm);
    const int tid = threadIdx.x, lane = tid & 31, wid = tid >> 5;
    const int m0 = blockIdx.x * 128, n0 = blockIdx.y * 128;
    const int wm = wid >> 2, wn = wid & 3;

    const int lrow = tid >> 1, lhalf = tid & 1;
    const __nv_bfloat16* Ag = A + (size_t)(m0 + lrow) * KCAT + lhalf * 32;
    const __nv_bfloat16* Bg = B + (size_t)(n0 + lrow) * KCAT + lhalf * 32;
    uint32_t swo[4];
#pragma unroll
    for (int j = 0; j < 4; j++) {
        uint32_t o = lrow * 128 + lhalf * 64 + j * 16;
        swo[j] = SW128(o);
    }

#define G1_ISSUE(it) do { \
    const int st_ = (it) % G1_STAGES; const int ke_ = (it) * G1_BKE; \
    const uint32_t so_ = sb + st_ * G1_STB; \
    _Pragma("unroll") \
    for (int j = 0; j < 4; j++) { \
        CPA16(so_ + swo[j],         Ag + ke_ + j * 8); \
        CPA16(so_ + 16384 + swo[j], Bg + ke_ + j * 8); \
    } } while (0)

    G1_ISSUE(0); CPA_COMMIT();
    G1_ISSUE(1); CPA_COMMIT();
    G1_ISSUE(2); CPA_COMMIT();

    float acc[4][4][4];
#pragma unroll
    for (int i = 0; i < 4; i++)
#pragma unroll
        for (int j = 0; j < 4; j++)
#pragma unroll
            for (int q = 0; q < 4; q++) acc[i][j][q] = 0.f;

    const int a_row = wm * 64 + (lane & 7) + 8 * ((lane >> 3) & 1);
    const uint32_t a_kb = (lane >> 4) * 16;
    const int b_row = wn * 32 + (lane & 7) + 8 * (lane >> 4);
    const uint32_t b_kb = ((lane >> 3) & 1) * 16;

    for (int it = 0; it < G1_KIT; it++) {
        CPA_WAIT2();
        __syncthreads();
        if (it + 3 < G1_KIT) G1_ISSUE(it + 3);
        CPA_COMMIT();

        const uint32_t ao = sb + (it % G1_STAGES) * G1_STB;
        const uint32_t bo = ao + 16384;
#pragma unroll
        for (int kk = 0; kk < 4; kk++) {
            uint32_t af[4][4], bf[2][4];
#pragma unroll
            for (int mt = 0; mt < 4; mt++) {
                uint32_t o = (uint32_t)(a_row + mt * 16) * 128 + kk * 32 + a_kb;
                ldm_x4(af[mt], ao + SW128(o));
            }
#pragma unroll
            for (int np = 0; np < 2; np++) {
                uint32_t o = (uint32_t)(b_row + np * 16) * 128 + kk * 32 + b_kb;
                ldm_x4(bf[np], bo + SW128(o));
            }
#pragma unroll
            for (int mt = 0; mt < 4; mt++)
#pragma unroll
                for (int nt = 0; nt < 4; nt++)
                    mma_bf16(acc[mt][nt], af[mt], &bf[nt >> 1][(nt & 1) * 2]);
        }
    }
    __syncthreads();

    const int erow = lane >> 2, ecol = (lane & 3) * 2;
#pragma unroll
    for (int mt = 0; mt < 4; mt++) {
        const int r0 = m0 + wm * 64 + mt * 16 + erow;
#pragma unroll
        for (int nt = 0; nt < 4; nt++) {
            const int c = n0 + wn * 32 + nt * 8 + ecol;
            float2 bb = *(const float2*)(bias + c);
            float v0 = acc[mt][nt][0] + bb.x, v1 = acc[mt][nt][1] + bb.y;
            float v2 = acc[mt][nt][2] + bb.x, v3 = acc[mt][nt][3] + bb.y;
            float2 o0 = { v0 > 0.f ? v0 : 0.01f * v0, v1 > 0.f ? v1 : 0.01f * v1 };
            float2 o1 = { v2 > 0.f ? v2 : 0.01f * v2, v3 > 0.f ? v3 : 0.01f * v3 };
            *(float2*)(C + (size_t)r0 * HDIM + c) = o0;
            *(float2*)(C + (size_t)(r0 + 8) * HDIM + c) = o1;
        }
    }
#undef G1_ISSUE
}

// ---------------- Fused GEMM2 + exp + Sinkhorn: one block per batch --------
// Both SMEM arrays padded to 68 floats/row (272 B = 17*16) so float4
// accesses are 16B-aligned for every row index.  (R6 crash: ws stride 66.)
__global__ __launch_bounds__(256) void g2sink_kernel(
    const float* __restrict__ h, const float* __restrict__ W2,
    const float* __restrict__ b2, float* __restrict__ P, float* __restrict__ out)
{
    __shared__ float hs[NN][68];
    __shared__ float ws[NN][68];
    __shared__ float sp[NN * NN];
    const int b = blockIdx.x, tid = threadIdx.x;
    const float* hb = h + (size_t)b * NN * HDIM;

    const int rg = tid / 5;            // row 0..49 (tid<250)
    const int c0 = (tid % 5) * 10;     // 10 cols per thread
    float acc[10];
#pragma unroll
    for (int j = 0; j < 10; j++) acc[j] = 0.f;

    for (int k0 = 0; k0 < HDIM; k0 += 64) {
        __syncthreads();
        for (int idx = tid; idx < NN * 64; idx += 256) {
            int r = idx >> 6, k = idx & 63;
            hs[r][k] = hb[(size_t)r * HDIM + k0 + k];
        }
        for (int idx = tid; idx < 64 * NN; idx += 256) {
            int k = idx / NN, c = idx % NN;
            ws[c][k] = W2[(size_t)(k0 + k) * NN + c];
        }
        __syncthreads();
        if (tid < 250) {
#pragma unroll
            for (int k = 0; k < 64; k += 4) {
                float4 a = *(const float4*)&hs[rg][k];
#pragma unroll
                for (int j = 0; j < 10; j++) {
                    float4 w = *(const float4*)&ws[c0 + j][k];
                    acc[j] = fmaf(a.x, w.x, acc[j]);
                    acc[j] = fmaf(a.y, w.y, acc[j]);
                    acc[j] = fmaf(a.z, w.z, acc[j]);
                    acc[j] = fmaf(a.w, w.w, acc[j]);
                }
            }
        }
    }
    __syncthreads();
    if (tid < 250) {
#pragma unroll
        for (int j = 0; j < 10; j++) {
            float s = acc[j] + b2[c0 + j];
            s = (s > 0.f) ? s : 0.01f * s;
            sp[rg * NN + c0 + j] = expf(s);
        }
    }
    __syncthreads();

    // Sinkhorn, 5 iters
    const int warp = tid >> 5, lane = tid & 31;
    for (int it = 0; it < 5; it++) {
        for (int i = warp; i < NN; i += 8) {
            float v0 = sp[i * NN + lane];
            float v1 = (lane + 32 < NN) ? sp[i * NN + lane + 32] : 0.f;
            float s = v0 + v1;
#pragma unroll
            for (int o = 16; o; o >>= 1) s += __shfl_xor_sync(~0u, s, o);
            sp[i * NN + lane] = v0 / s;
            if (lane + 32 < NN) sp[i * NN + lane + 32] = v1 / s;
        }
        __syncthreads();
        for (int j = warp; j < NN; j += 8) {
            float v0 = sp[lane * NN + j];
            float v1 = (lane + 32 < NN) ? sp[(lane + 32) * NN + j] : 0.f;
            float s = v0 + v1;
#pragma unroll
            for (int o = 16; o; o >>= 1) s += __shfl_xor_sync(~0u, s, o);
            sp[lane * NN + j] = v0 / s;
            if (lane + 32 < NN) sp[(lane + 32) * NN + j] = v1 / s;
        }
        __syncthreads();
    }
    float* psi_out = out + PSI_OFF + (size_t)b * NN * NN;
    float* x_out   = out + X_OFF   + (size_t)b * NN * NN;
    float* Pb      = P + (size_t)b * NN * NN;
    for (int i = tid; i < NN * NN; i += 256) {
        float v = sp[i];
        Pb[i] = v; psi_out[i] = v; x_out[i] = v;
    }
}

// ---------------- Hungarian v2: deferred potentials, register state --------
// Same buggy-greedy semantics as the numpy reference. Within a chain no u/v
// read depends on in-chain updates (u[i0] read in the marking iteration;
// free-col v untouched), so updates are applied once at chain end with the
// sequentially-accumulated delta sum (numpy rounding diff ~1e-16 << gaps).
__device__ __forceinline__ unsigned long long dsort(double d) {
    long long b = __double_as_longlong(d);
    return (b < 0) ? ~(unsigned long long)b
                   : ((unsigned long long)b | 0x8000000000000000ull);
}

__global__ __launch_bounds__(32) void hungarian_kernel(const float* __restrict__ P, float* __restrict__ out) {
    __shared__ float  sc[NN * NN];
    __shared__ double u_sh[NN + 1];
    __shared__ int    rtc[NN];
    const int b = blockIdx.x, lane = threadIdx.x;
    const double BIG = 1e18;
    const float* Pb = P + (size_t)b * NN * NN;

    for (int i = lane; i < NN * NN; i += 32) sc[i] = Pb[i];
    if (lane <= NN / 2) { u_sh[lane] = 0.0; u_sh[lane + 25] = 0.0; }
    // lane owns columns j=lane+1 (slot0) and j=lane+33 (slot1, lane<18)
    double v0 = 0.0, v1 = 0.0;
    int p0 = 0, p1 = 0;
    const bool has1 = (lane < 18);
    __syncwarp();

    for (int i = 1; i <= NN; i++) {
        bool used0 = false, used1 = !has1;
        double duse0 = 0.0, duse1 = 0.0;
        int way0 = 0, way1 = 0;
        double D = 0.0;
        int j0 = 0;

        while (true) {
            // mark j0 (col 0 = dummy, skip)
            if (j0) {
                if (j0 <= 32) { if (lane == j0 - 1) { used0 = true; duse0 = D; } }
                else          { if (lane == j0 - 33) { used1 = true; duse1 = D; } }
            }
            int i0;
            if (j0 == 0) i0 = i;
            else {
                int pa = __shfl_sync(~0u, p0, (j0 - 1) & 31);
                int pb = __shfl_sync(~0u, p1, (j0 - 33) & 31);
                i0 = (j0 <= 32) ? pa : pb;
            }
            const double ub = u_sh[i0];
            const float* row = sc + (i0 - 1) * NN;
            double c0d = used0 ? BIG : (-(double)row[lane] - ub - v0);
            double c1d = used1 ? BIG : (-(double)row[lane + 32] - ub - v1);

            unsigned long long k0 = (dsort(c0d) & ~63ull) | (unsigned)(lane + 1);
            unsigned long long k1 = (dsort(c1d) & ~63ull) | (unsigned)(lane + 33);
            unsigned long long km = (k0 < k1) ? k0 : k1;
            unsigned hi = (unsigned)(km >> 32);
            unsigned mh = __reduce_min_sync(~0u, hi);
            unsigned lo = (hi == mh) ? (unsigned)km : 0xFFFFFFFFu;
            unsigned ml = __reduce_min_sync(~0u, lo);
            const int j1 = ml & 63;

            double d0 = __shfl_sync(~0u, c0d, (j1 - 1) & 31);
            double d1 = __shfl_sync(~0u, c1d, (j1 - 33) & 31);
            D += (j1 <= 32) ? d0 : d1;

            if (j1 <= 32) { if (lane == j1 - 1) way0 = j0; }
            else          { if (lane == j1 - 33) way1 = j0; }

            int q0 = __shfl_sync(~0u, p0, (j1 - 1) & 31);
            int q1 = __shfl_sync(~0u, p1, (j1 - 33) & 31);
            const int pj1 = (j1 <= 32) ? q0 : q1;
            j0 = j1;
            if (pj1 == 0) break;
        }

        // deferred updates (distinct rows p[j] per used col -> conflict-free)
        if (used0) { double amt = D - duse0; v0 -= amt; u_sh[p0] += amt; }
        if (has1 && used1) { double amt = D - duse1; v1 -= amt; u_sh[p1] += amt; }
        if (lane == 0) u_sh[i] += D;    // col 0 (p[0]=i), used from step 1
        __syncwarp();

        // rotate matching along the chain
        int j = j0;
        while (j) {
            int wa = __shfl_sync(~0u, way0, (j - 1) & 31);
            int wb = __shfl_sync(~0u, way1, (j - 33) & 31);
            int jn = (j <= 32) ? wa : wb;
            int pn;
            if (jn == 0) pn = i;
            else {
                int qa = __shfl_sync(~0u, p0, (jn - 1) & 31);
                int qb = __shfl_sync(~0u, p1, (jn - 33) & 31);
                pn = (jn <= 32) ? qa : qb;
            }
            if (j <= 32) { if (lane == j - 1) p0 = pn; }
            else         { if (lane == j - 33) p1 = pn; }
            j = jn;
        }
    }

    if (p0 > 0) rtc[p0 - 1] = lane;
    if (has1 && p1 > 0) rtc[p1 - 1] = lane + 32;
    __syncwarp();

    float* pb = out + PERM_OFF + (size_t)b * NN * NN;
    for (int i = lane; i < NN * NN; i += 32) pb[i] = 0.f;
    __syncwarp();
    if (lane == 0) {
        float dsum = 0.f;
        for (int r = 0; r < NN; r++) { int c = rtc[r]; pb[r * NN + c] = 1.0f; dsum += sc[r * NN + c]; }
        out[DIST_OFF + b] = dsum / (float)NN;
    }
}

// ---------------------------------------------------------------------------
extern "C" void kernel_launch(void* const* d_in, const int* in_sizes, int n_in,
                              void* d_out, int out_size)
{
    (void)in_sizes; (void)n_in; (void)out_size;
    const float* x  = (const float*)d_in[0];
    const float* W1 = (const float*)d_in[1];
    const float* b1 = (const float*)d_in[2];
    const float* W2 = (const float*)d_in[3];
    const float* b2 = (const float*)d_in[4];
    float* out = (float*)d_out;

    float* h;  cudaGetSymbolAddress((void**)&h,  g_h);
    float* P;  cudaGetSymbolAddress((void**)&P,  g_P);
    __nv_bfloat16* Ac; cudaGetSymbolAddress((void**)&Ac, g_Acat);
    __nv_bfloat16* Bc; cudaGetSymbolAddress((void**)&Bc, g_Bcat);

    cudaFuncSetAttribute(gemm1_mma_kernel, cudaFuncAttributeMaxDynamicSharedMemorySize, G1_SMEM);

    split_x_kernel<<<MROWS * FDIM / 256, 256>>>(x, Ac);
    split_w_kernel<<<dim3(HDIM / 32, FDIM / 32), dim3(32, 8)>>>(W1, Bc);
    gemm1_mma_kernel<<<dim3(MROWS / 128, HDIM / 128), 256, G1_SMEM>>>(Ac, Bc, b1, h);
    g2sink_kernel<<<BATCH, 256>>>(h, W2, b2, P, out);
    hungarian_kernel<<<BATCH, 32>>>(P, out);
}

// round 8
// speedup vs baseline: 2.0689x; 1.5015x over previous
#include <cuda_runtime.h>
#include <cuda_bf16.h>
#include <math.h>
#include <stdint.h>

#define BATCH 128
#define NN    50
#define FDIM  1024
#define HDIM  4096
#define MROWS (BATCH*NN)
#define KCAT  (3*FDIM)          // 3072: slots [a0,a0,a1] x [b0,b1,b0]

#define PSI_OFF  0
#define PERM_OFF (BATCH*NN*NN)
#define X_OFF    (2*BATCH*NN*NN)
#define DIST_OFF (3*BATCH*NN*NN)

#define G2_SLICES 16
#define G2_KS     (HDIM / G2_SLICES)   // 256

__device__ float         g_h[(size_t)MROWS * HDIM];
__device__ float         g_P[BATCH * NN * NN];
__device__ float         g_part[(size_t)G2_SLICES * BATCH * NN * NN];
__device__ __nv_bfloat16 g_Acat[(size_t)MROWS * KCAT];
__device__ __nv_bfloat16 g_Bcat[(size_t)HDIM * KCAT];

__device__ __forceinline__ uint32_t smem_u32(const void* p) {
    uint32_t a;
    asm("{ .reg .u64 t; cvta.to.shared.u64 t, %1; cvt.u32.u64 %0, t; }" : "=r"(a) : "l"(p));
    return a;
}
#define SW128(o) ((o) ^ (((o) >> 3) & 0x70))
#define CPA16(dst, src) asm volatile("cp.async.cg.shared.global [%0], [%1], 16;" :: "r"(dst), "l"(src) : "memory")
#define CPA_COMMIT()    asm volatile("cp.async.commit_group;" ::: "memory")
#define CPA_WAIT2()     asm volatile("cp.async.wait_group 2;" ::: "memory")

__device__ __forceinline__ void ldm_x4(uint32_t* r, uint32_t addr) {
    asm volatile("ldmatrix.sync.aligned.m8n8.x4.shared.b16 {%0,%1,%2,%3}, [%4];"
        : "=r"(r[0]), "=r"(r[1]), "=r"(r[2]), "=r"(r[3]) : "r"(addr));
}
__device__ __forceinline__ void mma_bf16(float* d, const uint32_t* a, const uint32_t* b) {
    asm volatile("mma.sync.aligned.m16n8k16.row.col.f32.bf16.bf16.f32 "
        "{%0,%1,%2,%3}, {%4,%5,%6,%7}, {%8,%9}, {%0,%1,%2,%3};"
        : "+f"(d[0]), "+f"(d[1]), "+f"(d[2]), "+f"(d[3])
        : "r"(a[0]), "r"(a[1]), "r"(a[2]), "r"(a[3]), "r"(b[0]), "r"(b[1]));
}

// ---------------- split kernels (2-term bf16 split) ----------------
__global__ __launch_bounds__(256) void split_x_kernel(const float* __restrict__ x, __nv_bfloat16* __restrict__ A) {
    int idx = blockIdx.x * 256 + threadIdx.x;
    float a = x[idx];
    __nv_bfloat16 h0 = __float2bfloat16(a);
    __nv_bfloat16 h1 = __float2bfloat16(a - __bfloat162float(h0));
    __nv_bfloat16* row = A + (size_t)(idx >> 10) * KCAT + (idx & 1023);
    row[0] = h0; row[1024] = h0; row[2048] = h1;
}
__global__ __launch_bounds__(256) void split_w_kernel(const float* __restrict__ W1, __nv_bfloat16* __restrict__ B) {
    __shared__ __nv_bfloat16 t0[32][33], t1[32][33];
    const int tx = threadIdx.x, ty = threadIdx.y;   // (32,8)
    const int n0 = blockIdx.x * 32, k0 = blockIdx.y * 32;
#pragma unroll
    for (int i = 0; i < 4; i++) {
        int k = ty + i * 8;
        float w = W1[(size_t)(k0 + k) * HDIM + n0 + tx];
        __nv_bfloat16 h0 = __float2bfloat16(w);
        t0[k][tx] = h0;
        t1[k][tx] = __float2bfloat16(w - __bfloat162float(h0));
    }
    __syncthreads();
#pragma unroll
    for (int i = 0; i < 4; i++) {
        int n = ty + i * 8;
        __nv_bfloat16 b0 = t0[tx][n], b1 = t1[tx][n];
        __nv_bfloat16* row = B + (size_t)(n0 + n) * KCAT + k0 + tx;
        row[0] = b0; row[1024] = b1; row[2048] = b0;
    }
}

// ---------------- GEMM1: mma.sync bf16 (unchanged, passing) ----------------
#define G1_STAGES 4
#define G1_BKE    64
#define G1_KIT    (KCAT / G1_BKE)
#define G1_STB    32768
#define G1_SMEM   (G1_STAGES * G1_STB)

__global__ __launch_bounds__(256, 1) void gemm1_mma_kernel(
    const __nv_bfloat16* __restrict__ A, const __nv_bfloat16* __restrict__ B,
    const float* __restrict__ bias, float* __restrict__ C)
{
    extern __shared__ char sm[];
    const uint32_t sb = smem_u32(sm);
    const int tid = threadIdx.x, lane = tid & 31, wid = tid >> 5;
    const int m0 = blockIdx.x * 128, n0 = blockIdx.y * 128;
    const int wm = wid >> 2, wn = wid & 3;

    const int lrow = tid >> 1, lhalf = tid & 1;
    const __nv_bfloat16* Ag = A + (size_t)(m0 + lrow) * KCAT + lhalf * 32;
    const __nv_bfloat16* Bg = B + (size_t)(n0 + lrow) * KCAT + lhalf * 32;
    uint32_t swo[4];
#pragma unroll
    for (int j = 0; j < 4; j++) {
        uint32_t o = lrow * 128 + lhalf * 64 + j * 16;
        swo[j] = SW128(o);
    }

#define G1_ISSUE(it) do { \
    const int st_ = (it) % G1_STAGES; const int ke_ = (it) * G1_BKE; \
    const uint32_t so_ = sb + st_ * G1_STB; \
    _Pragma("unroll") \
    for (int j = 0; j < 4; j++) { \
        CPA16(so_ + swo[j],         Ag + ke_ + j * 8); \
        CPA16(so_ + 16384 + swo[j], Bg + ke_ + j * 8); \
    } } while (0)

    G1_ISSUE(0); CPA_COMMIT();
    G1_ISSUE(1); CPA_COMMIT();
    G1_ISSUE(2); CPA_COMMIT();

    float acc[4][4][4];
#pragma unroll
    for (int i = 0; i < 4; i++)
#pragma unroll
        for (int j = 0; j < 4; j++)
#pragma unroll
            for (int q = 0; q < 4; q++) acc[i][j][q] = 0.f;

    const int a_row = wm * 64 + (lane & 7) + 8 * ((lane >> 3) & 1);
    const uint32_t a_kb = (lane >> 4) * 16;
    const int b_row = wn * 32 + (lane & 7) + 8 * (lane >> 4);
    const uint32_t b_kb = ((lane >> 3) & 1) * 16;

    for (int it = 0; it < G1_KIT; it++) {
        CPA_WAIT2();
        __syncthreads();
        if (it + 3 < G1_KIT) G1_ISSUE(it + 3);
        CPA_COMMIT();

        const uint32_t ao = sb + (it % G1_STAGES) * G1_STB;
        const uint32_t bo = ao + 16384;
#pragma unroll
        for (int kk = 0; kk < 4; kk++) {
            uint32_t af[4][4], bf[2][4];
#pragma unroll
            for (int mt = 0; mt < 4; mt++) {
                uint32_t o = (uint32_t)(a_row + mt * 16) * 128 + kk * 32 + a_kb;
                ldm_x4(af[mt], ao + SW128(o));
            }
#pragma unroll
            for (int np = 0; np < 2; np++) {
                uint32_t o = (uint32_t)(b_row + np * 16) * 128 + kk * 32 + b_kb;
                ldm_x4(bf[np], bo + SW128(o));
            }
#pragma unroll
            for (int mt = 0; mt < 4; mt++)
#pragma unroll
                for (int nt = 0; nt < 4; nt++)
                    mma_bf16(acc[mt][nt], af[mt], &bf[nt >> 1][(nt & 1) * 2]);
        }
    }
    __syncthreads();

    const int erow = lane >> 2, ecol = (lane & 3) * 2;
#pragma unroll
    for (int mt = 0; mt < 4; mt++) {
        const int r0 = m0 + wm * 64 + mt * 16 + erow;
#pragma unroll
        for (int nt = 0; nt < 4; nt++) {
            const int c = n0 + wn * 32 + nt * 8 + ecol;
            float2 bb = *(const float2*)(bias + c);
            float v0 = acc[mt][nt][0] + bb.x, v1 = acc[mt][nt][1] + bb.y;
            float v2 = acc[mt][nt][2] + bb.x, v3 = acc[mt][nt][3] + bb.y;
            float2 o0 = { v0 > 0.f ? v0 : 0.01f * v0, v1 > 0.f ? v1 : 0.01f * v1 };
            float2 o1 = { v2 > 0.f ? v2 : 0.01f * v2, v3 > 0.f ? v3 : 0.01f * v3 };
            *(float2*)(C + (size_t)r0 * HDIM + c) = o0;
            *(float2*)(C + (size_t)(r0 + 8) * HDIM + c) = o1;
        }
    }
#undef G1_ISSUE
}

// ---------------- GEMM2 split-K: grid (128 batches, 16 slices) -------------
// 5x5 register tile per thread (tid<100): 10 LDS.128 per 100 FMA.
__global__ __launch_bounds__(128) void g2split_kernel(
    const float* __restrict__ h, const float* __restrict__ W2,
    float* __restrict__ part)
{
    __shared__ float hs[NN][68];
    __shared__ float ws[NN][68];
    const int b = blockIdx.x, s = blockIdx.y, tid = threadIdx.x;
    const int kbase = s * G2_KS;
    const float* hb = h + (size_t)b * NN * HDIM + kbase;

    const int r0 = (tid / 10) * 5, c0 = (tid % 10) * 5;   // tid<100
    float acc[5][5];
#pragma unroll
    for (int i = 0; i < 5; i++)
#pragma unroll
        for (int j = 0; j < 5; j++) acc[i][j] = 0.f;

    for (int kc = 0; kc < G2_KS; kc += 64) {
        __syncthreads();
        for (int idx = tid; idx < NN * 64; idx += 128) {
            int r = idx >> 6, k = idx & 63;
            hs[r][k] = hb[(size_t)r * HDIM + kc + k];
        }
        for (int idx = tid; idx < 64 * NN; idx += 128) {
            int k = idx / NN, c = idx % NN;
            ws[c][k] = W2[(size_t)(kbase + kc + k) * NN + c];
        }
        __syncthreads();
        if (tid < 100) {
#pragma unroll
            for (int k = 0; k < 64; k += 4) {
                float4 a[5];
#pragma unroll
                for (int i = 0; i < 5; i++) a[i] = *(const float4*)&hs[r0 + i][k];
#pragma unroll
                for (int j = 0; j < 5; j++) {
                    float4 w = *(const float4*)&ws[c0 + j][k];
#pragma unroll
                    for (int i = 0; i < 5; i++) {
                        acc[i][j] = fmaf(a[i].x, w.x, acc[i][j]);
                        acc[i][j] = fmaf(a[i].y, w.y, acc[i][j]);
                        acc[i][j] = fmaf(a[i].z, w.z, acc[i][j]);
                        acc[i][j] = fmaf(a[i].w, w.w, acc[i][j]);
                    }
                }
            }
        }
    }
    if (tid < 100) {
        float* pp = part + ((size_t)s * BATCH + b) * NN * NN;
#pragma unroll
        for (int i = 0; i < 5; i++)
#pragma unroll
            for (int j = 0; j < 5; j++)
                pp[(r0 + i) * NN + c0 + j] = acc[i][j];
    }
}

// ---------------- Reduce partials + bias/leaky/exp + Sinkhorn --------------
__global__ __launch_bounds__(256) void sinkreduce_kernel(
    const float* __restrict__ part, const float* __restrict__ b2,
    float* __restrict__ P, float* __restrict__ out)
{
    __shared__ float sp[NN * NN];
    const int b = blockIdx.x, tid = threadIdx.x;

    for (int i = tid; i < NN * NN; i += 256) {
        float m = 0.f;
#pragma unroll
        for (int s = 0; s < G2_SLICES; s++)
            m += part[((size_t)s * BATCH + b) * NN * NN + i];
        m += b2[i % NN];
        m = (m > 0.f) ? m : 0.01f * m;
        sp[i] = expf(m);
    }
    __syncthreads();

    const int warp = tid >> 5, lane = tid & 31;
    for (int it = 0; it < 5; it++) {
        for (int i = warp; i < NN; i += 8) {
            float v0 = sp[i * NN + lane];
            float v1 = (lane + 32 < NN) ? sp[i * NN + lane + 32] : 0.f;
            float s = v0 + v1;
#pragma unroll
            for (int o = 16; o; o >>= 1) s += __shfl_xor_sync(~0u, s, o);
            sp[i * NN + lane] = v0 / s;
            if (lane + 32 < NN) sp[i * NN + lane + 32] = v1 / s;
        }
        __syncthreads();
        for (int j = warp; j < NN; j += 8) {
            float v0 = sp[lane * NN + j];
            float v1 = (lane + 32 < NN) ? sp[(lane + 32) * NN + j] : 0.f;
            float s = v0 + v1;
#pragma unroll
            for (int o = 16; o; o >>= 1) s += __shfl_xor_sync(~0u, s, o);
            sp[lane * NN + j] = v0 / s;
            if (lane + 32 < NN) sp[(lane + 32) * NN + j] = v1 / s;
        }
        __syncthreads();
    }
    float* psi_out = out + PSI_OFF + (size_t)b * NN * NN;
    float* x_out   = out + X_OFF   + (size_t)b * NN * NN;
    float* Pb      = P + (size_t)b * NN * NN;
    for (int i = tid; i < NN * NN; i += 256) {
        float v = sp[i];
        Pb[i] = v; psi_out[i] = v; x_out[i] = v;
    }
}

// ---------------- Hungarian v2: deferred potentials, register state --------
__device__ __forceinline__ unsigned long long dsort(double d) {
    long long b = __double_as_longlong(d);
    return (b < 0) ? ~(unsigned long long)b
                   : ((unsigned long long)b | 0x8000000000000000ull);
}

__global__ __launch_bounds__(32) void hungarian_kernel(const float* __restrict__ P, float* __restrict__ out) {
    __shared__ float  sc[NN * NN];
    __shared__ double u_sh[NN + 1];
    __shared__ int    rtc[NN];
    const int b = blockIdx.x, lane = threadIdx.x;
    const double BIG = 1e18;
    const float* Pb = P + (size_t)b * NN * NN;

    for (int i = lane; i < NN * NN; i += 32) sc[i] = Pb[i];
    if (lane <= NN / 2) { u_sh[lane] = 0.0; u_sh[lane + 25] = 0.0; }
    double v0 = 0.0, v1 = 0.0;
    int p0 = 0, p1 = 0;
    const bool has1 = (lane < 18);
    __syncwarp();

    for (int i = 1; i <= NN; i++) {
        bool used0 = false, used1 = !has1;
        double duse0 = 0.0, duse1 = 0.0;
        int way0 = 0, way1 = 0;
        double D = 0.0;
        int j0 = 0;

        while (true) {
            if (j0) {
                if (j0 <= 32) { if (lane == j0 - 1) { used0 = true; duse0 = D; } }
                else          { if (lane == j0 - 33) { used1 = true; duse1 = D; } }
            }
            int i0;
            if (j0 == 0) i0 = i;
            else {
                int pa = __shfl_sync(~0u, p0, (j0 - 1) & 31);
                int pb = __shfl_sync(~0u, p1, (j0 - 33) & 31);
                i0 = (j0 <= 32) ? pa : pb;
            }
            const double ub = u_sh[i0];
            const float* row = sc + (i0 - 1) * NN;
            double c0d = used0 ? BIG : (-(double)row[lane] - ub - v0);
            double c1d = used1 ? BIG : (-(double)row[lane + 32] - ub - v1);

            unsigned long long k0 = (dsort(c0d) & ~63ull) | (unsigned)(lane + 1);
            unsigned long long k1 = (dsort(c1d) & ~63ull) | (unsigned)(lane + 33);
            unsigned long long km = (k0 < k1) ? k0 : k1;
            unsigned hi = (unsigned)(km >> 32);
            unsigned mh = __reduce_min_sync(~0u, hi);
            unsigned lo = (hi == mh) ? (unsigned)km : 0xFFFFFFFFu;
            unsigned ml = __reduce_min_sync(~0u, lo);
            const int j1 = ml & 63;

            double d0 = __shfl_sync(~0u, c0d, (j1 - 1) & 31);
            double d1 = __shfl_sync(~0u, c1d, (j1 - 33) & 31);
            D += (j1 <= 32) ? d0 : d1;

            if (j1 <= 32) { if (lane == j1 - 1) way0 = j0; }
            else          { if (lane == j1 - 33) way1 = j0; }

            int q0 = __shfl_sync(~0u, p0, (j1 - 1) & 31);
            int q1 = __shfl_sync(~0u, p1, (j1 - 33) & 31);
            const int pj1 = (j1 <= 32) ? q0 : q1;
            j0 = j1;
            if (pj1 == 0) break;
        }

        if (used0) { double amt = D - duse0; v0 -= amt; u_sh[p0] += amt; }
        if (has1 && used1) { double amt = D - duse1; v1 -= amt; u_sh[p1] += amt; }
        if (lane == 0) u_sh[i] += D;
        __syncwarp();

        int j = j0;
        while (j) {
            int wa = __shfl_sync(~0u, way0, (j - 1) & 31);
            int wb = __shfl_sync(~0u, way1, (j - 33) & 31);
            int jn = (j <= 32) ? wa : wb;
            int pn;
            if (jn == 0) pn = i;
            else {
                int qa = __shfl_sync(~0u, p0, (jn - 1) & 31);
                int qb = __shfl_sync(~0u, p1, (jn - 33) & 31);
                pn = (jn <= 32) ? qa : qb;
            }
            if (j <= 32) { if (lane == j - 1) p0 = pn; }
            else         { if (lane == j - 33) p1 = pn; }
            j = jn;
        }
    }

    if (p0 > 0) rtc[p0 - 1] = lane;
    if (has1 && p1 > 0) rtc[p1 - 1] = lane + 32;
    __syncwarp();

    float* pb = out + PERM_OFF + (size_t)b * NN * NN;
    for (int i = lane; i < NN * NN; i += 32) pb[i] = 0.f;
    __syncwarp();
    if (lane == 0) {
        float dsum = 0.f;
        for (int r = 0; r < NN; r++) { int c = rtc[r]; pb[r * NN + c] = 1.0f; dsum += sc[r * NN + c]; }
        out[DIST_OFF + b] = dsum / (float)NN;
    }
}

// ---------------------------------------------------------------------------
extern "C" void kernel_launch(void* const* d_in, const int* in_sizes, int n_in,
                              void* d_out, int out_size)
{
    (void)in_sizes; (void)n_in; (void)out_size;
    const float* x  = (const float*)d_in[0];
    const float* W1 = (const float*)d_in[1];
    const float* b1 = (const float*)d_in[2];
    const float* W2 = (const float*)d_in[3];
    const float* b2 = (const float*)d_in[4];
    float* out = (float*)d_out;

    float* h;  cudaGetSymbolAddress((void**)&h,  g_h);
    float* P;  cudaGetSymbolAddress((void**)&P,  g_P);
    float* pt; cudaGetSymbolAddress((void**)&pt, g_part);
    __nv_bfloat16* Ac; cudaGetSymbolAddress((void**)&Ac, g_Acat);
    __nv_bfloat16* Bc; cudaGetSymbolAddress((void**)&Bc, g_Bcat);

    cudaFuncSetAttribute(gemm1_mma_kernel, cudaFuncAttributeMaxDynamicSharedMemorySize, G1_SMEM);

    split_x_kernel<<<MROWS * FDIM / 256, 256>>>(x, Ac);
    split_w_kernel<<<dim3(HDIM / 32, FDIM / 32), dim3(32, 8)>>>(W1, Bc);
    gemm1_mma_kernel<<<dim3(MROWS / 128, HDIM / 128), 256, G1_SMEM>>>(Ac, Bc, b1, h);
    g2split_kernel<<<dim3(BATCH, G2_SLICES), 128>>>(h, W2, pt);
    sinkreduce_kernel<<<BATCH, 256>>>(pt, b2, P, out);
    hungarian_kernel<<<BATCH, 32>>>(P, out);
}